// round 7
// baseline (speedup 1.0000x reference)
#include <cuda_runtime.h>
#include <math.h>

#define NN 8192

// Scratch for partial dot products: 2 halves per row. Deterministic (indexed
// writes, no atomics). 64 KB static device memory (allowed; no allocation).
__device__ float g_partial[2 * NN];

// k1: half-row streaming. grid = 16384 CTAs (2 per row), 256 threads,
// 4 front-batched 128-bit w-loads per thread (16 KB of w per CTA).
// Short CTA lifetime -> finer tail granularity; low regs -> full occupancy.
__device__ __forceinline__ float4 ldg_stream_noL1(const float4* p) {
    float4 r;
    asm("ld.global.nc.L1::no_allocate.v4.f32 {%0,%1,%2,%3}, [%4];"
        : "=f"(r.x), "=f"(r.y), "=f"(r.z), "=f"(r.w)
        : "l"(p));
    return r;
}

__global__ void __launch_bounds__(256, 8) izh_dot_kernel(
    const float* __restrict__ g,
    const float* __restrict__ w)
{
    const int bid  = blockIdx.x;
    const int row  = bid >> 1;
    const int half = bid & 1;
    const int base = half * 1024;  // in float4 units; a row is 2048 float4

    const float4* __restrict__ wrow = reinterpret_cast<const float4*>(w + (size_t)row * NN);
    const float4* __restrict__ g4   = reinterpret_cast<const float4*>(g);

    float sum = 0.0f;
    #pragma unroll
    for (int i = 0; i < 4; ++i) {
        const int idx = base + threadIdx.x + i * 256;
        const float4 a = ldg_stream_noL1(&wrow[idx]);  // streaming, no L1 alloc
        const float4 b = __ldg(&g4[idx]);              // L1-resident
        sum += a.x * b.x;
        sum += a.y * b.y;
        sum += a.z * b.z;
        sum += a.w * b.w;
    }

    #pragma unroll
    for (int off = 16; off > 0; off >>= 1)
        sum += __shfl_xor_sync(0xffffffffu, sum, off);

    __shared__ float ssum[8];
    const int wid = threadIdx.x >> 5;
    if ((threadIdx.x & 31) == 0) ssum[wid] = sum;
    __syncthreads();

    if (threadIdx.x == 0) {
        float dot = 0.0f;
        #pragma unroll
        for (int i = 0; i < 8; ++i) dot += ssum[i];
        g_partial[bid] = dot;
    }
}

// k2: pointwise Izhikevich epilogue, one thread per neuron, fully coalesced.
__global__ void __launch_bounds__(256) izh_epilogue_kernel(
    const float* __restrict__ x_in,
    const float* __restrict__ v,
    const float* __restrict__ u,
    const float* __restrict__ g,
    const float* __restrict__ a_p,
    const float* __restrict__ b_p,
    const float* __restrict__ c_p,
    const float* __restrict__ d_p,
    float* __restrict__ out)
{
    const int r = blockIdx.x * 256 + threadIdx.x;

    const float I  = g_partial[2 * r] + g_partial[2 * r + 1] + x_in[r];
    const float vv = v[r];
    const float uu = u[r];
    const float gg = g[r];

    // Izhikevich quadratic dynamics
    const float v1 = vv + (0.04f * vv * vv + 5.0f * vv + 140.0f - uu + I);

    // differentiable spike surrogate: sigmoid(4 * (v1 - 30))
    const float s = 1.0f / (1.0f + expf(-4.0f * (v1 - 30.0f)));

    // hard spike mask for state resets
    const float spk = (v1 >= 30.0f) ? 1.0f : 0.0f;
    const float ns  = 1.0f - spk;

    const float du = fabsf(a_p[r]) * (fabsf(b_p[r]) * v1 - uu);
    const float dg = -gg / 6.5f;

    out[r]           = ns * v1 + spk * c_p[r];           // v_out
    out[NN + r]      = s;                                 // spiked_s
    out[2 * NN + r]  = ns * (uu + du) + spk * d_p[r];     // u_out
    out[3 * NN + r]  = ns * (gg + dg) + spk;              // g_out
}

extern "C" void kernel_launch(void* const* d_in, const int* in_sizes, int n_in,
                              void* d_out, int out_size)
{
    const float* x_in = (const float*)d_in[0];
    const float* v    = (const float*)d_in[1];
    const float* u    = (const float*)d_in[2];
    const float* g    = (const float*)d_in[3];
    const float* w    = (const float*)d_in[4];
    const float* a_p  = (const float*)d_in[5];
    const float* b_p  = (const float*)d_in[6];
    const float* c_p  = (const float*)d_in[7];
    const float* d_p  = (const float*)d_in[8];
    float* out = (float*)d_out;

    izh_dot_kernel<<<2 * NN, 256>>>(g, w);
    izh_epilogue_kernel<<<NN / 256, 256>>>(x_in, v, u, g, a_p, b_p, c_p, d_p, out);
}